// round 2
// baseline (speedup 1.0000x reference)
#include <cuda_runtime.h>
#include <math.h>

#define Bn   128
#define Cc   256
#define Np   4096
#define CQ   64
#define BN_EPS 1e-5f

// ---------------- scratch (no allocations allowed) ----------------
__device__ float g_tk[Bn * CQ];        // tanh(x_k)   (128*64)
__device__ float g_energy[Bn * Np];    // 2 MB
__device__ float g_y[Bn * Cc];         // x @ att
__device__ float g_d[Bn * Cc];         // x_key - x_r

// ---------------- kernel 0: tk = tanh(wk @ x_key + bk) ----------------
__global__ void tk_kernel(const float* __restrict__ xk,
                          const float* __restrict__ wk,
                          const float* __restrict__ bk,
                          float* __restrict__ tk) {
    __shared__ float xs[Cc];
    int b = blockIdx.x;
    for (int i = threadIdx.x; i < Cc; i += blockDim.x) xs[i] = xk[b * Cc + i];
    __syncthreads();
    int o = threadIdx.x;
    if (o < CQ) {
        float s = bk[o];
        const float* wr = wk + o * Cc;
        #pragma unroll 8
        for (int c = 0; c < Cc; ++c) s += wr[c] * xs[c];
        tk[b * CQ + o] = tanhf(s);
    }
}

// ---------------- kernel A: energy[b,n] = sum_o tanh(q[b,n,o]) * tk[b,o] ----------------
// block: (16 n-tiles x 128 batches), 256 threads = 64 n-threads x 4 o-groups.
// Each thread: 4 consecutive n's x 16 o's -> 64 fp32 accumulators.
// dyn smem: wq_s[C][CQ] (64KB, transposed, o contiguous) + xs[32][256] (32KB) + tk_s[64]
__global__ void __launch_bounds__(256)
energy_kernel(const float* __restrict__ x,
              const float* __restrict__ wq,
              const float* __restrict__ bq,
              const float* __restrict__ tk,
              float* __restrict__ energy) {
    extern __shared__ float sm[];
    float* wq_s = sm;                    // 16384 floats, [c][o]
    float* xs   = sm + Cc * CQ;          // 8192 floats, [cc][n_local]
    float* tk_s = xs + 32 * 256;         // 64 floats

    const int tid = threadIdx.x;
    const int b   = blockIdx.y;
    const int n0  = blockIdx.x * 256;

    // stage wq transposed: wq[o][c] (c contiguous) -> wq_s[c][o]
    for (int e = tid; e < Cc * CQ; e += 256) {
        int o = e >> 8;            // / 256
        int c = e & 255;
        wq_s[c * CQ + o] = wq[e];
    }
    if (tid < CQ) tk_s[tid] = tk[b * CQ + tid];
    __syncthreads();

    const int nt = tid & 63;   // n-thread: points n0 + 4*nt .. +3
    const int og = tid >> 6;   // o-group: outputs og*16 .. +15

    float q[4][16];
    {
        float bqv[16];
        #pragma unroll
        for (int k = 0; k < 16; ++k) bqv[k] = bq[og * 16 + k];
        #pragma unroll
        for (int j = 0; j < 4; ++j)
            #pragma unroll
            for (int k = 0; k < 16; ++k) q[j][k] = bqv[k];
    }

    const float4* wq4 = (const float4*)wq_s;
    float4* xs4w = (float4*)xs;
    const float4* xs4 = (const float4*)xs;

    for (int ch = 0; ch < 8; ++ch) {
        __syncthreads();
        // stage x[b, ch*32 .. +32, n0 .. n0+256) -> xs[32][256]
        const float4* xg = (const float4*)(x + ((size_t)b * Cc + ch * 32) * Np + n0);
        #pragma unroll
        for (int f = 0; f < 8; ++f) {
            int idx = f * 256 + tid;            // 2048 float4 total
            int cc  = idx >> 6;                 // / 64
            int j   = idx & 63;
            xs4w[idx] = xg[(size_t)cc * (Np / 4) + j];
        }
        __syncthreads();

        #pragma unroll 8
        for (int cc = 0; cc < 32; ++cc) {
            float4 xv = xs4[cc * 64 + nt];
            int c = ch * 32 + cc;
            float4 w0 = wq4[c * 16 + og * 4 + 0];
            float4 w1 = wq4[c * 16 + og * 4 + 1];
            float4 w2 = wq4[c * 16 + og * 4 + 2];
            float4 w3 = wq4[c * 16 + og * 4 + 3];
            float xvv[4] = {xv.x, xv.y, xv.z, xv.w};
            float wv_[16] = {w0.x, w0.y, w0.z, w0.w,
                             w1.x, w1.y, w1.z, w1.w,
                             w2.x, w2.y, w2.z, w2.w,
                             w3.x, w3.y, w3.z, w3.w};
            #pragma unroll
            for (int j = 0; j < 4; ++j)
                #pragma unroll
                for (int k = 0; k < 16; ++k)
                    q[j][k] = fmaf(xvv[j], wv_[k], q[j][k]);
        }
    }

    // partial energy over this thread's 16 o's
    float ep[4];
    #pragma unroll
    for (int j = 0; j < 4; ++j) {
        float s = 0.f;
        #pragma unroll
        for (int k = 0; k < 16; ++k) s += tanhf(q[j][k]) * tk_s[og * 16 + k];
        ep[j] = s;
    }

    __syncthreads();
    float* red = xs;  // reuse: [4 og][256 points]
    #pragma unroll
    for (int j = 0; j < 4; ++j) red[og * 256 + nt * 4 + j] = ep[j];
    __syncthreads();
    if (og == 0) {
        #pragma unroll
        for (int j = 0; j < 4; ++j) {
            int p = nt * 4 + j;
            float e = red[p] + red[256 + p] + red[512 + p] + red[768 + p];
            energy[(size_t)b * Np + n0 + p] = e;
        }
    }
}

// ---------------- kernel B: attention = softmax(energy, axis=n) ----------------
__global__ void softmax_kernel(const float* __restrict__ energy,
                               float* __restrict__ att) {
    __shared__ float red[256];
    int b = blockIdx.x, t = threadIdx.x;
    const float4* e4 = (const float4*)(energy + (size_t)b * Np);
    float4 v[4];
    float m = -INFINITY;
    #pragma unroll
    for (int k = 0; k < 4; ++k) {
        v[k] = e4[k * 256 + t];
        m = fmaxf(m, fmaxf(fmaxf(v[k].x, v[k].y), fmaxf(v[k].z, v[k].w)));
    }
    red[t] = m; __syncthreads();
    for (int off = 128; off; off >>= 1) {
        if (t < off) red[t] = fmaxf(red[t], red[t + off]);
        __syncthreads();
    }
    m = red[0]; __syncthreads();

    float s = 0.f;
    #pragma unroll
    for (int k = 0; k < 4; ++k)
        s += expf(v[k].x - m) + expf(v[k].y - m) + expf(v[k].z - m) + expf(v[k].w - m);
    red[t] = s; __syncthreads();
    for (int off = 128; off; off >>= 1) {
        if (t < off) red[t] += red[t + off];
        __syncthreads();
    }
    float inv = 1.f / red[0];

    float4* a4 = (float4*)(att + (size_t)b * Np);
    #pragma unroll
    for (int k = 0; k < 4; ++k) {
        float4 o;
        o.x = expf(v[k].x - m) * inv;
        o.y = expf(v[k].y - m) * inv;
        o.z = expf(v[k].z - m) * inv;
        o.w = expf(v[k].w - m) * inv;
        a4[k * 256 + t] = o;
    }
}

// ---------------- kernel C: y[b,c] = sum_n x[b,c,n] * att[b,n] ----------------
// grid (C/4, B), 256 threads; att row staged in smem, 4 channels per block.
__global__ void yacc_kernel(const float* __restrict__ x,
                            const float* __restrict__ att,
                            float* __restrict__ y) {
    __shared__ float att_s[Np];
    __shared__ float red[256];
    int b = blockIdx.y, cg = blockIdx.x, t = threadIdx.x;
    const float4* a4 = (const float4*)(att + (size_t)b * Np);
    float4* as4 = (float4*)att_s;
    #pragma unroll
    for (int k = 0; k < 4; ++k) as4[k * 256 + t] = a4[k * 256 + t];
    __syncthreads();

    for (int chn = 0; chn < 4; ++chn) {
        int c = cg * 4 + chn;
        const float4* xg = (const float4*)(x + ((size_t)b * Cc + c) * Np);
        float acc = 0.f;
        #pragma unroll
        for (int k = 0; k < 4; ++k) {
            float4 xv = xg[k * 256 + t];
            float4 av = as4[k * 256 + t];
            acc += xv.x * av.x + xv.y * av.y + xv.z * av.z + xv.w * av.w;
        }
        red[t] = acc; __syncthreads();
        for (int off = 128; off; off >>= 1) {
            if (t < off) red[t] += red[t + off];
            __syncthreads();
        }
        if (t == 0) y[b * Cc + c] = red[0];
        __syncthreads();
    }
}

// ---------------- kernel D1: d = x_key - (wv @ y + bv) ----------------
// grid B, 256 threads (8 warps); warp computes 32 outputs via coalesced warp dots.
__global__ void d_kernel(const float* __restrict__ xk,
                         const float* __restrict__ wv,
                         const float* __restrict__ bv,
                         const float* __restrict__ y,
                         float* __restrict__ d) {
    __shared__ float ys[Cc];
    int b = blockIdx.x, t = threadIdx.x;
    ys[t] = y[b * Cc + t];
    __syncthreads();
    int warp = t >> 5, lane = t & 31;
    for (int i = 0; i < 32; ++i) {
        int c = warp * 32 + i;
        float s = 0.f;
        #pragma unroll
        for (int k = 0; k < 8; ++k) {
            int cp = k * 32 + lane;
            s += wv[(size_t)c * Cc + cp] * ys[cp];
        }
        #pragma unroll
        for (int off = 16; off; off >>= 1) s += __shfl_down_sync(0xFFFFFFFFu, s, off);
        if (lane == 0) d[b * Cc + c] = xk[b * Cc + c] - (s + bv[c]);
    }
}

// ---------------- kernel D2: t = wt@d + bt; BN over batch; out = x_key + relu(t_hat) ----
// grid C, 128 threads (4 warps); warp computes 32 batch rows via coalesced warp dots.
__global__ void bn_out_kernel(const float* __restrict__ d,
                              const float* __restrict__ wt,
                              const float* __restrict__ bt,
                              const float* __restrict__ gamma,
                              const float* __restrict__ beta,
                              const float* __restrict__ xk,
                              float* __restrict__ out) {
    __shared__ float wts[Cc];
    __shared__ float ts[Bn];
    __shared__ float r1[Bn];
    __shared__ float r2[Bn];
    int c = blockIdx.x, t = threadIdx.x;
    wts[t] = wt[(size_t)c * Cc + t];
    wts[t + 128] = wt[(size_t)c * Cc + t + 128];
    __syncthreads();
    int warp = t >> 5, lane = t & 31;
    for (int i = 0; i < 32; ++i) {
        int b = warp * 32 + i;
        float s = 0.f;
        #pragma unroll
        for (int k = 0; k < 8; ++k) {
            int cp = k * 32 + lane;
            s += wts[cp] * d[b * Cc + cp];
        }
        #pragma unroll
        for (int off = 16; off; off >>= 1) s += __shfl_down_sync(0xFFFFFFFFu, s, off);
        if (lane == 0) ts[b] = s + bt[c];
    }
    __syncthreads();
    float tv = ts[t];
    r1[t] = tv; r2[t] = tv * tv;
    __syncthreads();
    for (int off = 64; off; off >>= 1) {
        if (t < off) { r1[t] += r1[t + off]; r2[t] += r2[t + off]; }
        __syncthreads();
    }
    float mean = r1[0] * (1.f / Bn);
    float var  = r2[0] * (1.f / Bn) - mean * mean;
    float nrm  = (tv - mean) * rsqrtf(var + BN_EPS) * gamma[c] + beta[c];
    out[t * Cc + c] = xk[t * Cc + c] + fmaxf(nrm, 0.f);
}

// ---------------- launch ----------------
extern "C" void kernel_launch(void* const* d_in, const int* in_sizes, int n_in,
                              void* d_out, int out_size) {
    const float* x     = (const float*)d_in[0];
    const float* xkey  = (const float*)d_in[1];
    const float* wq    = (const float*)d_in[2];
    const float* bq    = (const float*)d_in[3];
    const float* wk    = (const float*)d_in[4];
    const float* bk    = (const float*)d_in[5];
    const float* wv    = (const float*)d_in[6];
    const float* bv    = (const float*)d_in[7];
    const float* wt    = (const float*)d_in[8];
    const float* bt    = (const float*)d_in[9];
    const float* gamma = (const float*)d_in[10];
    const float* beta  = (const float*)d_in[11];

    float* out_final = (float*)d_out;             // (B, C)
    float* out_att   = (float*)d_out + Bn * Cc;   // (B, N)

    float *tk, *energy, *y, *dd;
    cudaGetSymbolAddress((void**)&tk,     g_tk);
    cudaGetSymbolAddress((void**)&energy, g_energy);
    cudaGetSymbolAddress((void**)&y,      g_y);
    cudaGetSymbolAddress((void**)&dd,     g_d);

    const size_t esmem = (Cc * CQ + 32 * 256 + 64) * sizeof(float);  // 98560
    cudaFuncSetAttribute(energy_kernel, cudaFuncAttributeMaxDynamicSharedMemorySize, (int)esmem);

    tk_kernel<<<Bn, 64>>>(xkey, wk, bk, tk);
    energy_kernel<<<dim3(Np / 256, Bn), 256, esmem>>>(x, wq, bq, tk, energy);
    softmax_kernel<<<Bn, 256>>>(energy, out_att);
    yacc_kernel<<<dim3(Cc / 4, Bn), 256>>>(x, out_att, y);
    d_kernel<<<Bn, 256>>>(xkey, wv, bv, y, dd);
    bn_out_kernel<<<Cc, 128>>>(dd, wt, bt, gamma, beta, xkey, out_final);
}

// round 3
// speedup vs baseline: 1.0365x; 1.0365x over previous
#include <cuda_runtime.h>
#include <math.h>

#define Bn   128
#define Cc   256
#define Np   4096
#define CQ   64
#define BN_EPS 1e-5f

// ---------------- scratch (no allocations allowed) ----------------
__device__ float g_tk[Bn * CQ];        // tanh(x_k)   (128*64)
__device__ float g_energy[Bn * Np];    // 2 MB
__device__ float g_y[Bn * Cc];         // x @ att
__device__ float g_d[Bn * Cc];         // x_key - x_r

// ---------------- packed f32x2 helpers (sm_10x FFMA2 path) ----------------
__device__ __forceinline__ unsigned long long pack2(float a, float b) {
    unsigned long long r;
    asm("mov.b64 %0, {%1, %2};" : "=l"(r) : "f"(a), "f"(b));
    return r;
}
__device__ __forceinline__ void unpack2(unsigned long long v, float& a, float& b) {
    asm("mov.b64 {%0, %1}, %2;" : "=f"(a), "=f"(b) : "l"(v));
}
__device__ __forceinline__ void ffma2(unsigned long long& d,
                                      unsigned long long a,
                                      unsigned long long b) {
    asm("fma.rn.f32x2 %0, %1, %2, %0;" : "+l"(d) : "l"(a), "l"(b));
}

// ---------------- kernel 0: tk = tanh(wk @ x_key + bk) ----------------
__global__ void tk_kernel(const float* __restrict__ xk,
                          const float* __restrict__ wk,
                          const float* __restrict__ bk,
                          float* __restrict__ tk) {
    __shared__ float xs[Cc];
    int b = blockIdx.x;
    for (int i = threadIdx.x; i < Cc; i += blockDim.x) xs[i] = xk[b * Cc + i];
    __syncthreads();
    int o = threadIdx.x;
    if (o < CQ) {
        float s = bk[o];
        const float* wr = wk + o * Cc;
        #pragma unroll 8
        for (int c = 0; c < Cc; ++c) s += wr[c] * xs[c];
        tk[b * CQ + o] = tanhf(s);
    }
}

// ---------------- kernel A: energy[b,n] = sum_o tanh(q[b,n,o]) * tk[b,o] ----------------
// block: (16 n-tiles x 128 batches), 256 threads = 64 n-threads x 4 o-groups.
// Each thread: 4 consecutive n's x 16 o's -> 32 packed f32x2 accumulators.
// dyn smem: wq_s[C][CQ] (64KB, transposed, o contiguous) + xs[32][256] (32KB) + tk_s[64]
__global__ void __launch_bounds__(256)
energy_kernel(const float* __restrict__ x,
              const float* __restrict__ wq,
              const float* __restrict__ bq,
              const float* __restrict__ tk,
              float* __restrict__ energy) {
    extern __shared__ float sm[];
    float* wq_s = sm;                    // 16384 floats, [c][o]
    float* xs   = sm + Cc * CQ;          // 8192 floats, [cc][n_local]
    float* tk_s = xs + 32 * 256;         // 64 floats

    const int tid = threadIdx.x;
    const int b   = blockIdx.y;
    const int n0  = blockIdx.x * 256;

    // stage wq transposed: wq[o][c] (c contiguous) -> wq_s[c][o]
    for (int e = tid; e < Cc * CQ; e += 256) {
        int o = e >> 8;            // / 256
        int c = e & 255;
        wq_s[c * CQ + o] = wq[e];
    }
    if (tid < CQ) tk_s[tid] = tk[b * CQ + tid];
    __syncthreads();

    const int nt = tid & 63;   // n-thread: points n0 + 4*nt .. +3
    const int og = tid >> 6;   // o-group: outputs og*16 .. +15

    // acc[j][kp]: j = n index (0..3), kp = o-pair (0..7), packed {o=2kp, o=2kp+1}
    unsigned long long acc[4][8];
    {
        #pragma unroll
        for (int kp = 0; kp < 8; ++kp) {
            unsigned long long bqp = pack2(bq[og * 16 + 2 * kp], bq[og * 16 + 2 * kp + 1]);
            #pragma unroll
            for (int j = 0; j < 4; ++j) acc[j][kp] = bqp;
        }
    }

    float4* xs4w = (float4*)xs;
    const float4* xs4 = (const float4*)xs;

    for (int ch = 0; ch < 8; ++ch) {
        __syncthreads();
        // stage x[b, ch*32 .. +32, n0 .. n0+256) -> xs[32][256]
        const float4* xg = (const float4*)(x + ((size_t)b * Cc + ch * 32) * Np + n0);
        #pragma unroll
        for (int f = 0; f < 8; ++f) {
            int idx = f * 256 + tid;            // 2048 float4 total
            int cc  = idx >> 6;                 // / 64
            int j   = idx & 63;
            xs4w[idx] = xg[(size_t)cc * (Np / 4) + j];
        }
        __syncthreads();

        #pragma unroll 4
        for (int cc = 0; cc < 32; ++cc) {
            float4 xv = xs4[cc * 64 + nt];
            int c = ch * 32 + cc;
            // 16 weights for this (c, og): already o-contiguous -> 8 aligned 64-bit words
            const unsigned long long* wrow =
                (const unsigned long long*)(wq_s + c * CQ + og * 16);
            unsigned long long w[8];
            #pragma unroll
            for (int kp = 0; kp < 8; ++kp) w[kp] = wrow[kp];
            unsigned long long xb[4];
            xb[0] = pack2(xv.x, xv.x);
            xb[1] = pack2(xv.y, xv.y);
            xb[2] = pack2(xv.z, xv.z);
            xb[3] = pack2(xv.w, xv.w);
            #pragma unroll
            for (int j = 0; j < 4; ++j)
                #pragma unroll
                for (int kp = 0; kp < 8; ++kp)
                    ffma2(acc[j][kp], xb[j], w[kp]);
        }
    }

    // partial energy over this thread's 16 o's
    float ep[4];
    #pragma unroll
    for (int j = 0; j < 4; ++j) {
        float s = 0.f;
        #pragma unroll
        for (int kp = 0; kp < 8; ++kp) {
            float qa, qb;
            unpack2(acc[j][kp], qa, qb);
            s += tanhf(qa) * tk_s[og * 16 + 2 * kp];
            s += tanhf(qb) * tk_s[og * 16 + 2 * kp + 1];
        }
        ep[j] = s;
    }

    __syncthreads();
    float* red = xs;  // reuse: [4 og][256 points]
    #pragma unroll
    for (int j = 0; j < 4; ++j) red[og * 256 + nt * 4 + j] = ep[j];
    __syncthreads();
    if (og == 0) {
        #pragma unroll
        for (int j = 0; j < 4; ++j) {
            int p = nt * 4 + j;
            float e = red[p] + red[256 + p] + red[512 + p] + red[768 + p];
            energy[(size_t)b * Np + n0 + p] = e;
        }
    }
}

// ---------------- kernel B: attention = softmax(energy, axis=n) ----------------
__global__ void softmax_kernel(const float* __restrict__ energy,
                               float* __restrict__ att) {
    __shared__ float red[256];
    int b = blockIdx.x, t = threadIdx.x;
    const float4* e4 = (const float4*)(energy + (size_t)b * Np);
    float4 v[4];
    float m = -INFINITY;
    #pragma unroll
    for (int k = 0; k < 4; ++k) {
        v[k] = e4[k * 256 + t];
        m = fmaxf(m, fmaxf(fmaxf(v[k].x, v[k].y), fmaxf(v[k].z, v[k].w)));
    }
    red[t] = m; __syncthreads();
    for (int off = 128; off; off >>= 1) {
        if (t < off) red[t] = fmaxf(red[t], red[t + off]);
        __syncthreads();
    }
    m = red[0]; __syncthreads();

    float s = 0.f;
    #pragma unroll
    for (int k = 0; k < 4; ++k)
        s += expf(v[k].x - m) + expf(v[k].y - m) + expf(v[k].z - m) + expf(v[k].w - m);
    red[t] = s; __syncthreads();
    for (int off = 128; off; off >>= 1) {
        if (t < off) red[t] += red[t + off];
        __syncthreads();
    }
    float inv = 1.f / red[0];

    float4* a4 = (float4*)(att + (size_t)b * Np);
    #pragma unroll
    for (int k = 0; k < 4; ++k) {
        float4 o;
        o.x = expf(v[k].x - m) * inv;
        o.y = expf(v[k].y - m) * inv;
        o.z = expf(v[k].z - m) * inv;
        o.w = expf(v[k].w - m) * inv;
        a4[k * 256 + t] = o;
    }
}

// ---------------- kernel C: y[b,c] = sum_n x[b,c,n] * att[b,n] ----------------
// grid (C/4, B), 256 threads; att row staged in smem, 4 channels per block.
__global__ void yacc_kernel(const float* __restrict__ x,
                            const float* __restrict__ att,
                            float* __restrict__ y) {
    __shared__ float att_s[Np];
    __shared__ float red[256];
    int b = blockIdx.y, cg = blockIdx.x, t = threadIdx.x;
    const float4* a4 = (const float4*)(att + (size_t)b * Np);
    float4* as4 = (float4*)att_s;
    #pragma unroll
    for (int k = 0; k < 4; ++k) as4[k * 256 + t] = a4[k * 256 + t];
    __syncthreads();

    for (int chn = 0; chn < 4; ++chn) {
        int c = cg * 4 + chn;
        const float4* xg = (const float4*)(x + ((size_t)b * Cc + c) * Np);
        float acc = 0.f;
        #pragma unroll
        for (int k = 0; k < 4; ++k) {
            float4 xv = xg[k * 256 + t];
            float4 av = as4[k * 256 + t];
            acc += xv.x * av.x + xv.y * av.y + xv.z * av.z + xv.w * av.w;
        }
        red[t] = acc; __syncthreads();
        for (int off = 128; off; off >>= 1) {
            if (t < off) red[t] += red[t + off];
            __syncthreads();
        }
        if (t == 0) y[b * Cc + c] = red[0];
        __syncthreads();
    }
}

// ---------------- kernel D1: d = x_key - (wv @ y + bv) ----------------
__global__ void d_kernel(const float* __restrict__ xk,
                         const float* __restrict__ wv,
                         const float* __restrict__ bv,
                         const float* __restrict__ y,
                         float* __restrict__ d) {
    __shared__ float ys[Cc];
    int b = blockIdx.x, t = threadIdx.x;
    ys[t] = y[b * Cc + t];
    __syncthreads();
    int warp = t >> 5, lane = t & 31;
    for (int i = 0; i < 32; ++i) {
        int c = warp * 32 + i;
        float s = 0.f;
        #pragma unroll
        for (int k = 0; k < 8; ++k) {
            int cp = k * 32 + lane;
            s += wv[(size_t)c * Cc + cp] * ys[cp];
        }
        #pragma unroll
        for (int off = 16; off; off >>= 1) s += __shfl_down_sync(0xFFFFFFFFu, s, off);
        if (lane == 0) d[b * Cc + c] = xk[b * Cc + c] - (s + bv[c]);
    }
}

// ---------------- kernel D2: t = wt@d + bt; BN over batch; out = x_key + relu(t_hat) ----
__global__ void bn_out_kernel(const float* __restrict__ d,
                              const float* __restrict__ wt,
                              const float* __restrict__ bt,
                              const float* __restrict__ gamma,
                              const float* __restrict__ beta,
                              const float* __restrict__ xk,
                              float* __restrict__ out) {
    __shared__ float wts[Cc];
    __shared__ float ts[Bn];
    __shared__ float r1[Bn];
    __shared__ float r2[Bn];
    int c = blockIdx.x, t = threadIdx.x;
    wts[t] = wt[(size_t)c * Cc + t];
    wts[t + 128] = wt[(size_t)c * Cc + t + 128];
    __syncthreads();
    int warp = t >> 5, lane = t & 31;
    for (int i = 0; i < 32; ++i) {
        int b = warp * 32 + i;
        float s = 0.f;
        #pragma unroll
        for (int k = 0; k < 8; ++k) {
            int cp = k * 32 + lane;
            s += wts[cp] * d[b * Cc + cp];
        }
        #pragma unroll
        for (int off = 16; off; off >>= 1) s += __shfl_down_sync(0xFFFFFFFFu, s, off);
        if (lane == 0) ts[b] = s + bt[c];
    }
    __syncthreads();
    float tv = ts[t];
    r1[t] = tv; r2[t] = tv * tv;
    __syncthreads();
    for (int off = 64; off; off >>= 1) {
        if (t < off) { r1[t] += r1[t + off]; r2[t] += r2[t + off]; }
        __syncthreads();
    }
    float mean = r1[0] * (1.f / Bn);
    float var  = r2[0] * (1.f / Bn) - mean * mean;
    float nrm  = (tv - mean) * rsqrtf(var + BN_EPS) * gamma[c] + beta[c];
    out[t * Cc + c] = xk[t * Cc + c] + fmaxf(nrm, 0.f);
}

// ---------------- launch ----------------
extern "C" void kernel_launch(void* const* d_in, const int* in_sizes, int n_in,
                              void* d_out, int out_size) {
    const float* x     = (const float*)d_in[0];
    const float* xkey  = (const float*)d_in[1];
    const float* wq    = (const float*)d_in[2];
    const float* bq    = (const float*)d_in[3];
    const float* wk    = (const float*)d_in[4];
    const float* bk    = (const float*)d_in[5];
    const float* wv    = (const float*)d_in[6];
    const float* bv    = (const float*)d_in[7];
    const float* wt    = (const float*)d_in[8];
    const float* bt    = (const float*)d_in[9];
    const float* gamma = (const float*)d_in[10];
    const float* beta  = (const float*)d_in[11];

    float* out_final = (float*)d_out;             // (B, C)
    float* out_att   = (float*)d_out + Bn * Cc;   // (B, N)

    float *tk, *energy, *y, *dd;
    cudaGetSymbolAddress((void**)&tk,     g_tk);
    cudaGetSymbolAddress((void**)&energy, g_energy);
    cudaGetSymbolAddress((void**)&y,      g_y);
    cudaGetSymbolAddress((void**)&dd,     g_d);

    const size_t esmem = (Cc * CQ + 32 * 256 + 64) * sizeof(float);  // 98560
    cudaFuncSetAttribute(energy_kernel, cudaFuncAttributeMaxDynamicSharedMemorySize, (int)esmem);

    tk_kernel<<<Bn, 64>>>(xkey, wk, bk, tk);
    energy_kernel<<<dim3(Np / 256, Bn), 256, esmem>>>(x, wq, bq, tk, energy);
    softmax_kernel<<<Bn, 256>>>(energy, out_att);
    yacc_kernel<<<dim3(Cc / 4, Bn), 256>>>(x, out_att, y);
    d_kernel<<<Bn, 256>>>(xkey, wv, bv, y, dd);
    bn_out_kernel<<<Cc, 128>>>(dd, wt, bt, gamma, beta, xkey, out_final);
}

// round 5
// speedup vs baseline: 1.5373x; 1.4833x over previous
#include <cuda_runtime.h>
#include <math.h>
#include <stdint.h>

#define Bn   128
#define Cc   256
#define Np   4096
#define CQ   64
#define BN_EPS 1e-5f

// ---------------- scratch (no allocations allowed) ----------------
__device__ float g_tk[Bn * CQ];
__device__ float g_energy[Bn * Np];
__device__ float g_y[Bn * Cc];
__device__ float g_d[Bn * Cc];

// ---------------- helpers ----------------
__device__ __forceinline__ uint32_t smem_u32(const void* p) {
    uint32_t a;
    asm("{ .reg .u64 t; cvta.to.shared.u64 t, %1; cvt.u32.u64 %0, t; }" : "=r"(a) : "l"(p));
    return a;
}
// pack high halves of two fp32 words: d = {a.hi16, b.hi16} (a in low half)
__device__ __forceinline__ uint32_t prmt_hi(uint32_t a, uint32_t b) {
    uint32_t d;
    asm("prmt.b32 %0, %1, %2, 0x7632;" : "=r"(d) : "r"(a), "r"(b));
    return d;
}
__device__ __forceinline__ void ldsm4(uint32_t (&r)[4], uint32_t addr) {
    asm volatile("ldmatrix.sync.aligned.m8n8.x4.shared.b16 {%0,%1,%2,%3}, [%4];"
                 : "=r"(r[0]), "=r"(r[1]), "=r"(r[2]), "=r"(r[3]) : "r"(addr));
}
__device__ __forceinline__ void ldsm4t(uint32_t (&r)[4], uint32_t addr) {
    asm volatile("ldmatrix.sync.aligned.m8n8.x4.trans.shared.b16 {%0,%1,%2,%3}, [%4];"
                 : "=r"(r[0]), "=r"(r[1]), "=r"(r[2]), "=r"(r[3]) : "r"(addr));
}
__device__ __forceinline__ void mma16816(float (&c)[4], const uint32_t (&a)[4],
                                         uint32_t b0, uint32_t b1) {
    asm volatile(
        "mma.sync.aligned.m16n8k16.row.col.f32.bf16.bf16.f32 "
        "{%0,%1,%2,%3}, {%4,%5,%6,%7}, {%8,%9}, {%0,%1,%2,%3};"
        : "+f"(c[0]), "+f"(c[1]), "+f"(c[2]), "+f"(c[3])
        : "r"(a[0]), "r"(a[1]), "r"(a[2]), "r"(a[3]), "r"(b0), "r"(b1));
}
// split float4 into packed bf16 hi pair + lo pair (truncation split; exact to ~2^-16)
__device__ __forceinline__ void split4(float4 v, uint32_t& h01, uint32_t& h23,
                                       uint32_t& l01, uint32_t& l23) {
    uint32_t ax = __float_as_uint(v.x), ay = __float_as_uint(v.y);
    uint32_t az = __float_as_uint(v.z), aw = __float_as_uint(v.w);
    h01 = prmt_hi(ax, ay);
    h23 = prmt_hi(az, aw);
    float lx = v.x - __uint_as_float(ax & 0xFFFF0000u);
    float ly = v.y - __uint_as_float(ay & 0xFFFF0000u);
    float lz = v.z - __uint_as_float(az & 0xFFFF0000u);
    float lw = v.w - __uint_as_float(aw & 0xFFFF0000u);
    l01 = prmt_hi(__float_as_uint(lx), __float_as_uint(ly));
    l23 = prmt_hi(__float_as_uint(lz), __float_as_uint(lw));
}

// smem layout (bytes). Row stride 264 halves = 528 B (16B-aligned, conflict-free ldmatrix)
#define RSTR      264
#define OFF_WQH   0                        // 64 x 264 halves = 33792
#define OFF_WQL   33792
#define OFF_XH    67584                    // 64 x 264 halves (one 64-c chunk)
#define OFF_XL    101376
#define OFF_TK    135168                   // 64 floats
#define OFF_BQ    135424                   // 64 floats
#define ESMEM     135680

// ---------------- kernel 0: tk = tanh(wk @ x_key + bk) ----------------
__global__ void tk_kernel(const float* __restrict__ xk,
                          const float* __restrict__ wk,
                          const float* __restrict__ bk,
                          float* __restrict__ tk) {
    __shared__ float xs[Cc];
    int b = blockIdx.x;
    for (int i = threadIdx.x; i < Cc; i += blockDim.x) xs[i] = xk[b * Cc + i];
    __syncthreads();
    int o = threadIdx.x;
    if (o < CQ) {
        float s = bk[o];
        const float* wr = wk + o * Cc;
        #pragma unroll 8
        for (int c = 0; c < Cc; ++c) s += wr[c] * xs[c];
        tk[b * CQ + o] = tanhf(s);
    }
}

// ---------------- kernel A: HMMA energy ----------------
// grid (16, 128): CTA = (b, 256-n tile). 8 warps x 32 n each.
// q[o][n] = sum_c wq[o][c] x[b][c][n];  energy[n] = sum_o tanh(q+bq[o]) * tk[b][o]
__global__ void __launch_bounds__(256)
energy_kernel(const float* __restrict__ x,
              const float* __restrict__ wq,
              const float* __restrict__ bq,
              const float* __restrict__ tk,
              float* __restrict__ energy) {
    extern __shared__ char sm[];
    const uint32_t sb = smem_u32(sm);
    const int tid  = threadIdx.x;
    const int warp = tid >> 5;
    const int lane = tid & 31;
    const int b    = blockIdx.y;
    const int n0   = blockIdx.x * 256;

    float* tk_s = (float*)(sm + OFF_TK);
    float* bq_s = (float*)(sm + OFF_BQ);
    if (tid < CQ) {
        tk_s[tid] = tk[b * CQ + tid];
        bq_s[tid] = bq[tid];
    }

    // ---- stage wq hi/lo: [o][c], row stride RSTR halves ----
    {
        const float4* wq4 = (const float4*)wq;
        #pragma unroll
        for (int f = 0; f < 16; ++f) {
            int idx = f * 256 + tid;       // 4096 float4 = 64 o x 64 j (c=4j)
            int o = idx >> 6;
            int j = idx & 63;
            float4 v = wq4[idx];
            uint32_t h01, h23, l01, l23;
            split4(v, h01, h23, l01, l23);
            uint32_t off = (uint32_t)o * (RSTR * 2) + j * 8;
            *(uint2*)(sm + OFF_WQH + off) = make_uint2(h01, h23);
            *(uint2*)(sm + OFF_WQL + off) = make_uint2(l01, l23);
        }
    }
    __syncthreads();

    // accumulators: m-tiles (o) x n-tiles x c-frag
    float acc[4][4][4];
    #pragma unroll
    for (int mt = 0; mt < 4; ++mt)
        #pragma unroll
        for (int nt = 0; nt < 4; ++nt)
            #pragma unroll
            for (int e = 0; e < 4; ++e) acc[mt][nt][e] = 0.f;

    // lane offsets for ldmatrix
    const uint32_t a_off = (uint32_t)(lane & 15) * 528 + (uint32_t)(lane >> 4) * 16;
    const uint32_t b_off = (uint32_t)(((lane >> 3) & 1) * 8 + (lane & 7)) * 528
                         + (uint32_t)(lane >> 4) * 16 + (uint32_t)warp * 64;

    const float* xg = x + ((size_t)b * Cc) * Np + n0;

    for (int ch = 0; ch < 4; ++ch) {
        // ---- stage x chunk: c in [ch*64, +64), n in [n0, n0+256) ----
        #pragma unroll
        for (int f = 0; f < 16; ++f) {
            int idx = f * 256 + tid;       // 4096 float4 = 64 c x 64 j (n=4j)
            int c = idx >> 6;
            int j = idx & 63;
            float4 v = *(const float4*)(xg + ((size_t)(ch * 64 + c)) * Np + 4 * j);
            uint32_t h01, h23, l01, l23;
            split4(v, h01, h23, l01, l23);
            uint32_t off = (uint32_t)c * (RSTR * 2) + j * 8;
            *(uint2*)(sm + OFF_XH + off) = make_uint2(h01, h23);
            *(uint2*)(sm + OFF_XL + off) = make_uint2(l01, l23);
        }
        __syncthreads();

        #pragma unroll
        for (int kk = 0; kk < 4; ++kk) {
            uint32_t c_b = (uint32_t)(ch * 64 + kk * 16) * 2;   // byte col into wq rows
            uint32_t krow = (uint32_t)(kk * 16) * 528;          // byte row into x chunk

            uint32_t a_hi[4][4], a_lo[4][4];
            #pragma unroll
            for (int mt = 0; mt < 4; ++mt) {
                ldsm4(a_hi[mt], sb + OFF_WQH + (uint32_t)mt * (16 * 528) + c_b + a_off);
                ldsm4(a_lo[mt], sb + OFF_WQL + (uint32_t)mt * (16 * 528) + c_b + a_off);
            }
            uint32_t b_hi[2][4], b_lo[2][4];
            #pragma unroll
            for (int ntp = 0; ntp < 2; ++ntp) {
                ldsm4t(b_hi[ntp], sb + OFF_XH + krow + (uint32_t)ntp * 32 + b_off);
                ldsm4t(b_lo[ntp], sb + OFF_XL + krow + (uint32_t)ntp * 32 + b_off);
            }
            #pragma unroll
            for (int mt = 0; mt < 4; ++mt)
                #pragma unroll
                for (int nt = 0; nt < 4; ++nt) {
                    int ntp = nt >> 1, hb = (nt & 1) * 2;
                    mma16816(acc[mt][nt], a_hi[mt], b_hi[ntp][hb], b_hi[ntp][hb + 1]);
                    mma16816(acc[mt][nt], a_hi[mt], b_lo[ntp][hb], b_lo[ntp][hb + 1]);
                    mma16816(acc[mt][nt], a_lo[mt], b_hi[ntp][hb], b_hi[ntp][hb + 1]);
                }
        }
        __syncthreads();
    }

    // ---- epilogue: tanh, dot with tk, reduce over o ----
    const int r = lane >> 2;
    float s0[4] = {0.f, 0.f, 0.f, 0.f};
    float s1[4] = {0.f, 0.f, 0.f, 0.f};
    #pragma unroll
    for (int mt = 0; mt < 4; ++mt) {
        float bq1 = bq_s[mt * 16 + r],     tk1 = tk_s[mt * 16 + r];
        float bq2 = bq_s[mt * 16 + r + 8], tk2 = tk_s[mt * 16 + r + 8];
        #pragma unroll
        for (int nt = 0; nt < 4; ++nt) {
            s0[nt] += tanhf(acc[mt][nt][0] + bq1) * tk1 + tanhf(acc[mt][nt][2] + bq2) * tk2;
            s1[nt] += tanhf(acc[mt][nt][1] + bq1) * tk1 + tanhf(acc[mt][nt][3] + bq2) * tk2;
        }
    }
    #pragma unroll
    for (int nt = 0; nt < 4; ++nt) {
        #pragma unroll
        for (int d = 4; d < 32; d <<= 1) {
            s0[nt] += __shfl_xor_sync(0xFFFFFFFFu, s0[nt], d);
            s1[nt] += __shfl_xor_sync(0xFFFFFFFFu, s1[nt], d);
        }
    }
    if (lane < 4) {
        #pragma unroll
        for (int nt = 0; nt < 4; ++nt) {
            int n = n0 + warp * 32 + nt * 8 + 2 * lane;
            *(float2*)(energy + (size_t)b * Np + n) = make_float2(s0[nt], s1[nt]);
        }
    }
}

// ---------------- kernel B: softmax ----------------
__global__ void softmax_kernel(const float* __restrict__ energy,
                               float* __restrict__ att) {
    __shared__ float red[256];
    int b = blockIdx.x, t = threadIdx.x;
    const float4* e4 = (const float4*)(energy + (size_t)b * Np);
    float4 v[4];
    float m = -INFINITY;
    #pragma unroll
    for (int k = 0; k < 4; ++k) {
        v[k] = e4[k * 256 + t];
        m = fmaxf(m, fmaxf(fmaxf(v[k].x, v[k].y), fmaxf(v[k].z, v[k].w)));
    }
    red[t] = m; __syncthreads();
    for (int off = 128; off; off >>= 1) {
        if (t < off) red[t] = fmaxf(red[t], red[t + off]);
        __syncthreads();
    }
    m = red[0]; __syncthreads();
    float s = 0.f;
    #pragma unroll
    for (int k = 0; k < 4; ++k)
        s += expf(v[k].x - m) + expf(v[k].y - m) + expf(v[k].z - m) + expf(v[k].w - m);
    red[t] = s; __syncthreads();
    for (int off = 128; off; off >>= 1) {
        if (t < off) red[t] += red[t + off];
        __syncthreads();
    }
    float inv = 1.f / red[0];
    float4* a4 = (float4*)(att + (size_t)b * Np);
    #pragma unroll
    for (int k = 0; k < 4; ++k) {
        float4 o;
        o.x = expf(v[k].x - m) * inv;
        o.y = expf(v[k].y - m) * inv;
        o.z = expf(v[k].z - m) * inv;
        o.w = expf(v[k].w - m) * inv;
        a4[k * 256 + t] = o;
    }
}

// ---------------- kernel C: y[b,c] = sum_n x[b,c,n]*att[b,n] ----------------
__global__ void yacc_kernel(const float* __restrict__ x,
                            const float* __restrict__ att,
                            float* __restrict__ y) {
    __shared__ float att_s[Np];
    __shared__ float red[256];
    int b = blockIdx.y, cg = blockIdx.x, t = threadIdx.x;
    const float4* a4 = (const float4*)(att + (size_t)b * Np);
    float4* as4 = (float4*)att_s;
    #pragma unroll
    for (int k = 0; k < 4; ++k) as4[k * 256 + t] = a4[k * 256 + t];
    __syncthreads();
    for (int chn = 0; chn < 4; ++chn) {
        int c = cg * 4 + chn;
        const float4* xg = (const float4*)(x + ((size_t)b * Cc + c) * Np);
        float acc = 0.f;
        #pragma unroll
        for (int k = 0; k < 4; ++k) {
            float4 xv = xg[k * 256 + t];
            float4 av = as4[k * 256 + t];
            acc += xv.x * av.x + xv.y * av.y + xv.z * av.z + xv.w * av.w;
        }
        red[t] = acc; __syncthreads();
        for (int off = 128; off; off >>= 1) {
            if (t < off) red[t] += red[t + off];
            __syncthreads();
        }
        if (t == 0) y[b * Cc + c] = red[0];
        __syncthreads();
    }
}

// ---------------- kernel D1: d = x_key - (wv @ y + bv) ----------------
__global__ void d_kernel(const float* __restrict__ xk,
                         const float* __restrict__ wv,
                         const float* __restrict__ bv,
                         const float* __restrict__ y,
                         float* __restrict__ d) {
    __shared__ float ys[Cc];
    int b = blockIdx.x, t = threadIdx.x;
    ys[t] = y[b * Cc + t];
    __syncthreads();
    int warp = t >> 5, lane = t & 31;
    for (int i = 0; i < 32; ++i) {
        int c = warp * 32 + i;
        float s = 0.f;
        #pragma unroll
        for (int k = 0; k < 8; ++k) {
            int cp = k * 32 + lane;
            s += wv[(size_t)c * Cc + cp] * ys[cp];
        }
        #pragma unroll
        for (int off = 16; off; off >>= 1) s += __shfl_down_sync(0xFFFFFFFFu, s, off);
        if (lane == 0) d[b * Cc + c] = xk[b * Cc + c] - (s + bv[c]);
    }
}

// ---------------- kernel D2: BN + ReLU + residual ----------------
__global__ void bn_out_kernel(const float* __restrict__ d,
                              const float* __restrict__ wt,
                              const float* __restrict__ bt,
                              const float* __restrict__ gamma,
                              const float* __restrict__ beta,
                              const float* __restrict__ xk,
                              float* __restrict__ out) {
    __shared__ float wts[Cc];
    __shared__ float ts[Bn];
    __shared__ float r1[Bn];
    __shared__ float r2[Bn];
    int c = blockIdx.x, t = threadIdx.x;
    wts[t] = wt[(size_t)c * Cc + t];
    wts[t + 128] = wt[(size_t)c * Cc + t + 128];
    __syncthreads();
    int warp = t >> 5, lane = t & 31;
    for (int i = 0; i < 32; ++i) {
        int b = warp * 32 + i;
        float s = 0.f;
        #pragma unroll
        for (int k = 0; k < 8; ++k) {
            int cp = k * 32 + lane;
            s += wts[cp] * d[b * Cc + cp];
        }
        #pragma unroll
        for (int off = 16; off; off >>= 1) s += __shfl_down_sync(0xFFFFFFFFu, s, off);
        if (lane == 0) ts[b] = s + bt[c];
    }
    __syncthreads();
    float tv = ts[t];
    r1[t] = tv; r2[t] = tv * tv;
    __syncthreads();
    for (int off = 64; off; off >>= 1) {
        if (t < off) { r1[t] += r1[t + off]; r2[t] += r2[t + off]; }
        __syncthreads();
    }
    float mean = r1[0] * (1.f / Bn);
    float var  = r2[0] * (1.f / Bn) - mean * mean;
    float nrm  = (tv - mean) * rsqrtf(var + BN_EPS) * gamma[c] + beta[c];
    out[t * Cc + c] = xk[t * Cc + c] + fmaxf(nrm, 0.f);
}

// ---------------- launch ----------------
extern "C" void kernel_launch(void* const* d_in, const int* in_sizes, int n_in,
                              void* d_out, int out_size) {
    const float* x     = (const float*)d_in[0];
    const float* xkey  = (const float*)d_in[1];
    const float* wq    = (const float*)d_in[2];
    const float* bq    = (const float*)d_in[3];
    const float* wk    = (const float*)d_in[4];
    const float* bk    = (const float*)d_in[5];
    const float* wv    = (const float*)d_in[6];
    const float* bv    = (const float*)d_in[7];
    const float* wt    = (const float*)d_in[8];
    const float* bt    = (const float*)d_in[9];
    const float* gamma = (const float*)d_in[10];
    const float* beta  = (const float*)d_in[11];

    float* out_final = (float*)d_out;
    float* out_att   = (float*)d_out + Bn * Cc;

    float *tk, *energy, *y, *dd;
    cudaGetSymbolAddress((void**)&tk,     g_tk);
    cudaGetSymbolAddress((void**)&energy, g_energy);
    cudaGetSymbolAddress((void**)&y,      g_y);
    cudaGetSymbolAddress((void**)&dd,     g_d);

    cudaFuncSetAttribute(energy_kernel, cudaFuncAttributeMaxDynamicSharedMemorySize, ESMEM);

    tk_kernel<<<Bn, 64>>>(xkey, wk, bk, tk);
    energy_kernel<<<dim3(Np / 256, Bn), 256, ESMEM>>>(x, wq, bq, tk, energy);
    softmax_kernel<<<Bn, 256>>>(energy, out_att);
    yacc_kernel<<<dim3(Cc / 4, Bn), 256>>>(x, out_att, y);
    d_kernel<<<Bn, 256>>>(xkey, wv, bv, y, dd);
    bn_out_kernel<<<Cc, 128>>>(dd, wt, bt, gamma, beta, xkey, out_final);
}

// round 6
// speedup vs baseline: 1.8568x; 1.2078x over previous
#include <cuda_runtime.h>
#include <math.h>
#include <stdint.h>

#define Bn   128
#define Cc   256
#define Np   4096
#define CQ   64
#define BN_EPS 1e-5f
#define NT   128                 // n-tile per CTA
#define NTILES (Np / NT)         // 32

// ---------------- scratch (no allocations allowed) ----------------
__device__ float g_tk[Bn * CQ];
__device__ float g_energy[Bn * Np];
__device__ float g_yp[Bn * NTILES * Cc];   // per-tile unnormalized y partials (4 MB)
__device__ float g_zp[Bn * NTILES];        // per-tile sum of exp(e)
__device__ float g_d[Bn * Cc];

// ---------------- helpers ----------------
__device__ __forceinline__ uint32_t smem_u32(const void* p) {
    uint32_t a;
    asm("{ .reg .u64 t; cvta.to.shared.u64 t, %1; cvt.u32.u64 %0, t; }" : "=r"(a) : "l"(p));
    return a;
}
__device__ __forceinline__ uint32_t prmt_hi(uint32_t a, uint32_t b) {
    uint32_t d;
    asm("prmt.b32 %0, %1, %2, 0x7632;" : "=r"(d) : "r"(a), "r"(b));
    return d;
}
__device__ __forceinline__ void ldsm4(uint32_t (&r)[4], uint32_t addr) {
    asm volatile("ldmatrix.sync.aligned.m8n8.x4.shared.b16 {%0,%1,%2,%3}, [%4];"
                 : "=r"(r[0]), "=r"(r[1]), "=r"(r[2]), "=r"(r[3]) : "r"(addr));
}
__device__ __forceinline__ void ldsm4t(uint32_t (&r)[4], uint32_t addr) {
    asm volatile("ldmatrix.sync.aligned.m8n8.x4.trans.shared.b16 {%0,%1,%2,%3}, [%4];"
                 : "=r"(r[0]), "=r"(r[1]), "=r"(r[2]), "=r"(r[3]) : "r"(addr));
}
__device__ __forceinline__ void mma16816(float (&c)[4], const uint32_t (&a)[4],
                                         uint32_t b0, uint32_t b1) {
    asm volatile(
        "mma.sync.aligned.m16n8k16.row.col.f32.bf16.bf16.f32 "
        "{%0,%1,%2,%3}, {%4,%5,%6,%7}, {%8,%9}, {%0,%1,%2,%3};"
        : "+f"(c[0]), "+f"(c[1]), "+f"(c[2]), "+f"(c[3])
        : "r"(a[0]), "r"(a[1]), "r"(a[2]), "r"(a[3]), "r"(b0), "r"(b1));
}
__device__ __forceinline__ void split4(float4 v, uint32_t& h01, uint32_t& h23,
                                       uint32_t& l01, uint32_t& l23) {
    uint32_t ax = __float_as_uint(v.x), ay = __float_as_uint(v.y);
    uint32_t az = __float_as_uint(v.z), aw = __float_as_uint(v.w);
    h01 = prmt_hi(ax, ay);
    h23 = prmt_hi(az, aw);
    float lx = v.x - __uint_as_float(ax & 0xFFFF0000u);
    float ly = v.y - __uint_as_float(ay & 0xFFFF0000u);
    float lz = v.z - __uint_as_float(az & 0xFFFF0000u);
    float lw = v.w - __uint_as_float(aw & 0xFFFF0000u);
    l01 = prmt_hi(__float_as_uint(lx), __float_as_uint(ly));
    l23 = prmt_hi(__float_as_uint(lz), __float_as_uint(lw));
}

// smem layout (bytes)
// wq: 64 rows (o) x 264 halves  -> stride 528 B
// x : 256 rows (c) x 136 halves -> stride 272 B
#define WSTRB     528
#define XSTRB     272
#define OFF_WQH   0                         // 64*528  = 33792
#define OFF_WQL   33792                     // 33792
#define OFF_XH    67584                     // 256*272 = 69632
#define OFF_XL    137216                    // 69632
#define OFF_E     206848                    // 128 floats
#define OFF_W     207360                    // 128 floats
#define OFF_TK    207872                    // 64 floats
#define OFF_BQ    208128                    // 64 floats
#define OFF_ZR    208384                    // 4 floats
#define ESMEM     208448

// ---------------- kernel 0: tk = tanh(wk @ x_key + bk) ----------------
__global__ void tk_kernel(const float* __restrict__ xk,
                          const float* __restrict__ wk,
                          const float* __restrict__ bk,
                          float* __restrict__ tk) {
    __shared__ float xs[Cc];
    int b = blockIdx.x;
    for (int i = threadIdx.x; i < Cc; i += blockDim.x) xs[i] = xk[b * Cc + i];
    __syncthreads();
    int o = threadIdx.x;
    if (o < CQ) {
        float s = bk[o];
        const float* wr = wk + o * Cc;
        #pragma unroll 8
        for (int c = 0; c < Cc; ++c) s += wr[c] * xs[c];
        tk[b * CQ + o] = tanhf(s);
    }
}

// ---------------- fused kernel: energy + exp + y partials ----------------
// grid (32, 128): CTA = (b, 128-n tile). 256 threads = 8 warps x 16 n.
__global__ void __launch_bounds__(256)
fused_kernel(const float* __restrict__ x,
             const float* __restrict__ wq,
             const float* __restrict__ bq,
             const float* __restrict__ tk,
             float* __restrict__ energy,
             float* __restrict__ yp,
             float* __restrict__ zp) {
    extern __shared__ char sm[];
    const uint32_t sb = smem_u32(sm);
    const int tid  = threadIdx.x;
    const int warp = tid >> 5;
    const int lane = tid & 31;
    const int b    = blockIdx.y;
    const int tile = blockIdx.x;
    const int n0   = tile * NT;

    float* tk_s = (float*)(sm + OFF_TK);
    float* bq_s = (float*)(sm + OFF_BQ);
    float* e_s  = (float*)(sm + OFF_E);
    float* w_s  = (float*)(sm + OFF_W);
    float* zr_s = (float*)(sm + OFF_ZR);
    if (tid < CQ) {
        tk_s[tid] = tk[b * CQ + tid];
        bq_s[tid] = bq[tid];
    }

    // ---- stage wq hi/lo ----
    {
        const float4* wq4 = (const float4*)wq;
        #pragma unroll
        for (int f = 0; f < 16; ++f) {
            int idx = f * 256 + tid;       // 4096 float4 = 64 o x 64 j (c=4j)
            int o = idx >> 6;
            int j = idx & 63;
            float4 v = wq4[idx];
            uint32_t h01, h23, l01, l23;
            split4(v, h01, h23, l01, l23);
            uint32_t off = (uint32_t)o * WSTRB + j * 8;
            *(uint2*)(sm + OFF_WQH + off) = make_uint2(h01, h23);
            *(uint2*)(sm + OFF_WQL + off) = make_uint2(l01, l23);
        }
    }

    // accumulators: 4 m-tiles (o) x 2 n-tiles x 4
    float acc[4][2][4];
    #pragma unroll
    for (int mt = 0; mt < 4; ++mt)
        #pragma unroll
        for (int nt = 0; nt < 2; ++nt)
            #pragma unroll
            for (int e = 0; e < 4; ++e) acc[mt][nt][e] = 0.f;

    const uint32_t a_off = (uint32_t)(lane & 15) * WSTRB + (uint32_t)(lane >> 4) * 16;
    const uint32_t b_off = (uint32_t)(((lane >> 3) & 1) * 8 + (lane & 7)) * XSTRB
                         + (uint32_t)(lane >> 4) * 16 + (uint32_t)warp * 32;

    const float* xg = x + ((size_t)b * Cc) * Np + n0;

    // thread's staging coords: chunk = 32 c's, 1024 float4, 4 per thread
    int sc[4], sj[4];
    #pragma unroll
    for (int f = 0; f < 4; ++f) {
        int idx = f * 256 + tid;
        sc[f] = idx >> 5;          // 0..31
        sj[f] = idx & 31;          // float4 col
    }

    // preload chunk 0
    float4 pre[4];
    #pragma unroll
    for (int f = 0; f < 4; ++f)
        pre[f] = *(const float4*)(xg + (size_t)sc[f] * Np + 4 * sj[f]);

    for (int ch = 0; ch < 8; ++ch) {
        // convert + store chunk ch
        #pragma unroll
        for (int f = 0; f < 4; ++f) {
            uint32_t h01, h23, l01, l23;
            split4(pre[f], h01, h23, l01, l23);
            uint32_t off = (uint32_t)(ch * 32 + sc[f]) * XSTRB + sj[f] * 8;
            *(uint2*)(sm + OFF_XH + off) = make_uint2(h01, h23);
            *(uint2*)(sm + OFF_XL + off) = make_uint2(l01, l23);
        }
        __syncthreads();

        // prefetch chunk ch+1 (latency hides under MMAs below)
        if (ch < 7) {
            #pragma unroll
            for (int f = 0; f < 4; ++f)
                pre[f] = *(const float4*)(xg + (size_t)((ch + 1) * 32 + sc[f]) * Np + 4 * sj[f]);
        }

        // MMA over chunk ch (k = 32 -> 2 slices of 16)
        #pragma unroll
        for (int kk = 0; kk < 2; ++kk) {
            uint32_t c_b  = (uint32_t)(ch * 32 + kk * 16) * 2;       // byte col into wq rows
            uint32_t krow = (uint32_t)(ch * 32 + kk * 16) * XSTRB;   // byte row into x

            uint32_t a_hi[4][4], a_lo[4][4];
            #pragma unroll
            for (int mt = 0; mt < 4; ++mt) {
                ldsm4(a_hi[mt], sb + OFF_WQH + (uint32_t)mt * (16 * WSTRB) + c_b + a_off);
                ldsm4(a_lo[mt], sb + OFF_WQL + (uint32_t)mt * (16 * WSTRB) + c_b + a_off);
            }
            uint32_t b_hi[4], b_lo[4];
            ldsm4t(b_hi, sb + OFF_XH + krow + b_off);
            ldsm4t(b_lo, sb + OFF_XL + krow + b_off);

            #pragma unroll
            for (int mt = 0; mt < 4; ++mt)
                #pragma unroll
                for (int nt = 0; nt < 2; ++nt) {
                    int hb = nt * 2;
                    mma16816(acc[mt][nt], a_hi[mt], b_hi[hb], b_hi[hb + 1]);
                    mma16816(acc[mt][nt], a_hi[mt], b_lo[hb], b_lo[hb + 1]);
                    mma16816(acc[mt][nt], a_lo[mt], b_hi[hb], b_hi[hb + 1]);
                }
        }
    }

    // ---- energy epilogue (warp-local: warp owns 16 n, all 64 o) ----
    {
        const int r = lane >> 2;
        float s0[2] = {0.f, 0.f};
        float s1[2] = {0.f, 0.f};
        #pragma unroll
        for (int mt = 0; mt < 4; ++mt) {
            float bq1 = bq_s[mt * 16 + r],     tk1 = tk_s[mt * 16 + r];
            float bq2 = bq_s[mt * 16 + r + 8], tk2 = tk_s[mt * 16 + r + 8];
            #pragma unroll
            for (int nt = 0; nt < 2; ++nt) {
                s0[nt] += tanhf(acc[mt][nt][0] + bq1) * tk1 + tanhf(acc[mt][nt][2] + bq2) * tk2;
                s1[nt] += tanhf(acc[mt][nt][1] + bq1) * tk1 + tanhf(acc[mt][nt][3] + bq2) * tk2;
            }
        }
        #pragma unroll
        for (int nt = 0; nt < 2; ++nt) {
            #pragma unroll
            for (int d = 4; d < 32; d <<= 1) {
                s0[nt] += __shfl_xor_sync(0xFFFFFFFFu, s0[nt], d);
                s1[nt] += __shfl_xor_sync(0xFFFFFFFFu, s1[nt], d);
            }
        }
        if (lane < 4) {
            #pragma unroll
            for (int nt = 0; nt < 2; ++nt) {
                int nl = warp * 16 + nt * 8 + 2 * lane;
                float2 ev = make_float2(s0[nt], s1[nt]);
                *(float2*)(e_s + nl) = ev;
                *(float2*)(energy + (size_t)b * Np + n0 + nl) = ev;
            }
        }
    }
    __syncthreads();

    // ---- w = exp(e) (no max shift: |e| < 64, no overflow) + Z partial ----
    if (tid < NT) {
        float w = expf(e_s[tid]);
        w_s[tid] = w;
        float s = w;
        #pragma unroll
        for (int d = 16; d; d >>= 1) s += __shfl_xor_sync(0xFFFFFFFFu, s, d);
        if (lane == 0) zr_s[tid >> 5] = s;
    }
    __syncthreads();
    if (tid == 0) zp[b * NTILES + tile] = zr_s[0] + zr_s[1] + zr_s[2] + zr_s[3];

    // ---- y partial: y_p[c] = sum_n x[c,n] * w[n]  (x = hi + lo from smem) ----
    {
        int c = tid;
        const uint2* hrow = (const uint2*)(sm + OFF_XH + (uint32_t)c * XSTRB);
        const uint2* lrow = (const uint2*)(sm + OFF_XL + (uint32_t)c * XSTRB);
        float accy = 0.f;
        #pragma unroll 8
        for (int j = 0; j < 32; ++j) {
            uint2 h = hrow[j];
            uint2 l = lrow[j];
            float4 w4 = *(const float4*)(w_s + 4 * j);
            float x0 = __uint_as_float(h.x << 16)         + __uint_as_float(l.x << 16);
            float x1 = __uint_as_float(h.x & 0xFFFF0000u) + __uint_as_float(l.x & 0xFFFF0000u);
            float x2 = __uint_as_float(h.y << 16)         + __uint_as_float(l.y << 16);
            float x3 = __uint_as_float(h.y & 0xFFFF0000u) + __uint_as_float(l.y & 0xFFFF0000u);
            accy = fmaf(x0, w4.x, accy);
            accy = fmaf(x1, w4.y, accy);
            accy = fmaf(x2, w4.z, accy);
            accy = fmaf(x3, w4.w, accy);
        }
        yp[((size_t)b * NTILES + tile) * Cc + c] = accy;
    }
}

// ---------------- kernel B: attention = softmax(energy) ----------------
__global__ void softmax_kernel(const float* __restrict__ energy,
                               float* __restrict__ att) {
    __shared__ float red[256];
    int b = blockIdx.x, t = threadIdx.x;
    const float4* e4 = (const float4*)(energy + (size_t)b * Np);
    float4 v[4];
    float m = -INFINITY;
    #pragma unroll
    for (int k = 0; k < 4; ++k) {
        v[k] = e4[k * 256 + t];
        m = fmaxf(m, fmaxf(fmaxf(v[k].x, v[k].y), fmaxf(v[k].z, v[k].w)));
    }
    red[t] = m; __syncthreads();
    for (int off = 128; off; off >>= 1) {
        if (t < off) red[t] = fmaxf(red[t], red[t + off]);
        __syncthreads();
    }
    m = red[0]; __syncthreads();
    float s = 0.f;
    #pragma unroll
    for (int k = 0; k < 4; ++k)
        s += expf(v[k].x - m) + expf(v[k].y - m) + expf(v[k].z - m) + expf(v[k].w - m);
    red[t] = s; __syncthreads();
    for (int off = 128; off; off >>= 1) {
        if (t < off) red[t] += red[t + off];
        __syncthreads();
    }
    float inv = 1.f / red[0];
    float4* a4 = (float4*)(att + (size_t)b * Np);
    #pragma unroll
    for (int k = 0; k < 4; ++k) {
        float4 o;
        o.x = expf(v[k].x - m) * inv;
        o.y = expf(v[k].y - m) * inv;
        o.z = expf(v[k].z - m) * inv;
        o.w = expf(v[k].w - m) * inv;
        a4[k * 256 + t] = o;
    }
}

// ---------------- kernel D1: reduce y partials; d = x_key - (wv @ y + bv) ----------------
__global__ void d_kernel(const float* __restrict__ xk,
                         const float* __restrict__ wv,
                         const float* __restrict__ bv,
                         const float* __restrict__ yp,
                         const float* __restrict__ zp,
                         float* __restrict__ d) {
    __shared__ float ys[Cc];
    int b = blockIdx.x, t = threadIdx.x;
    {
        float Z = 0.f;
        #pragma unroll 8
        for (int tt = 0; tt < NTILES; ++tt) Z += zp[b * NTILES + tt];
        float s = 0.f;
        #pragma unroll 8
        for (int tt = 0; tt < NTILES; ++tt)
            s += yp[((size_t)b * NTILES + tt) * Cc + t];
        ys[t] = s / Z;
    }
    __syncthreads();
    int warp = t >> 5, lane = t & 31;
    for (int i = 0; i < 32; ++i) {
        int c = warp * 32 + i;
        float s = 0.f;
        #pragma unroll
        for (int k = 0; k < 8; ++k) {
            int cp = k * 32 + lane;
            s += wv[(size_t)c * Cc + cp] * ys[cp];
        }
        #pragma unroll
        for (int off = 16; off; off >>= 1) s += __shfl_down_sync(0xFFFFFFFFu, s, off);
        if (lane == 0) d[b * Cc + c] = xk[b * Cc + c] - (s + bv[c]);
    }
}

// ---------------- kernel D2: BN + ReLU + residual ----------------
__global__ void bn_out_kernel(const float* __restrict__ d,
                              const float* __restrict__ wt,
                              const float* __restrict__ bt,
                              const float* __restrict__ gamma,
                              const float* __restrict__ beta,
                              const float* __restrict__ xk,
                              float* __restrict__ out) {
    __shared__ float wts[Cc];
    __shared__ float ts[Bn];
    __shared__ float r1[Bn];
    __shared__ float r2[Bn];
    int c = blockIdx.x, t = threadIdx.x;
    wts[t] = wt[(size_t)c * Cc + t];
    wts[t + 128] = wt[(size_t)c * Cc + t + 128];
    __syncthreads();
    int warp = t >> 5, lane = t & 31;
    for (int i = 0; i < 32; ++i) {
        int b = warp * 32 + i;
        float s = 0.f;
        #pragma unroll
        for (int k = 0; k < 8; ++k) {
            int cp = k * 32 + lane;
            s += wts[cp] * d[b * Cc + cp];
        }
        #pragma unroll
        for (int off = 16; off; off >>= 1) s += __shfl_down_sync(0xFFFFFFFFu, s, off);
        if (lane == 0) ts[b] = s + bt[c];
    }
    __syncthreads();
    float tv = ts[t];
    r1[t] = tv; r2[t] = tv * tv;
    __syncthreads();
    for (int off = 64; off; off >>= 1) {
        if (t < off) { r1[t] += r1[t + off]; r2[t] += r2[t + off]; }
        __syncthreads();
    }
    float mean = r1[0] * (1.f / Bn);
    float var  = r2[0] * (1.f / Bn) - mean * mean;
    float nrm  = (tv - mean) * rsqrtf(var + BN_EPS) * gamma[c] + beta[c];
    out[t * Cc + c] = xk[t * Cc + c] + fmaxf(nrm, 0.f);
}

// ---------------- launch ----------------
extern "C" void kernel_launch(void* const* d_in, const int* in_sizes, int n_in,
                              void* d_out, int out_size) {
    const float* x     = (const float*)d_in[0];
    const float* xkey  = (const float*)d_in[1];
    const float* wq    = (const float*)d_in[2];
    const float* bq    = (const float*)d_in[3];
    const float* wk    = (const float*)d_in[4];
    const float* bk    = (const float*)d_in[5];
    const float* wv    = (const float*)d_in[6];
    const float* bv    = (const float*)d_in[7];
    const float* wt    = (const float*)d_in[8];
    const float* bt    = (const float*)d_in[9];
    const float* gamma = (const float*)d_in[10];
    const float* beta  = (const float*)d_in[11];

    float* out_final = (float*)d_out;
    float* out_att   = (float*)d_out + Bn * Cc;

    float *tk, *energy, *yp, *zp, *dd;
    cudaGetSymbolAddress((void**)&tk,     g_tk);
    cudaGetSymbolAddress((void**)&energy, g_energy);
    cudaGetSymbolAddress((void**)&yp,     g_yp);
    cudaGetSymbolAddress((void**)&zp,     g_zp);
    cudaGetSymbolAddress((void**)&dd,     g_d);

    cudaFuncSetAttribute(fused_kernel, cudaFuncAttributeMaxDynamicSharedMemorySize, ESMEM);

    tk_kernel<<<Bn, 64>>>(xkey, wk, bk, tk);
    fused_kernel<<<dim3(NTILES, Bn), 256, ESMEM>>>(x, wq, bq, tk, energy, yp, zp);
    softmax_kernel<<<Bn, 256>>>(energy, out_att);
    d_kernel<<<Bn, 256>>>(xkey, wv, bv, yp, zp, dd);
    bn_out_kernel<<<Cc, 128>>>(dd, wt, bt, gamma, beta, xkey, out_final);
}

// round 7
// speedup vs baseline: 1.9435x; 1.0467x over previous
#include <cuda_runtime.h>
#include <cuda_fp16.h>
#include <math.h>
#include <stdint.h>

#define Bn   128
#define Cc   256
#define Np   4096
#define CQ   64
#define BN_EPS 1e-5f
#define NT   128                 // n-tile per CTA
#define NTILES (Np / NT)         // 32

// ---------------- scratch (no allocations allowed) ----------------
__device__ float g_tk[Bn * CQ];
__device__ float g_energy[Bn * Np];
__device__ float g_yp[Bn * NTILES * Cc];
__device__ float g_zp[Bn * NTILES];
__device__ float g_d[Bn * Cc];

// ---------------- helpers ----------------
__device__ __forceinline__ uint32_t smem_u32(const void* p) {
    uint32_t a;
    asm("{ .reg .u64 t; cvta.to.shared.u64 t, %1; cvt.u32.u64 %0, t; }" : "=r"(a) : "l"(p));
    return a;
}
__device__ __forceinline__ void ldsm4(uint32_t (&r)[4], uint32_t addr) {
    asm volatile("ldmatrix.sync.aligned.m8n8.x4.shared.b16 {%0,%1,%2,%3}, [%4];"
                 : "=r"(r[0]), "=r"(r[1]), "=r"(r[2]), "=r"(r[3]) : "r"(addr));
}
__device__ __forceinline__ void ldsm4t(uint32_t (&r)[4], uint32_t addr) {
    asm volatile("ldmatrix.sync.aligned.m8n8.x4.trans.shared.b16 {%0,%1,%2,%3}, [%4];"
                 : "=r"(r[0]), "=r"(r[1]), "=r"(r[2]), "=r"(r[3]) : "r"(addr));
}
__device__ __forceinline__ void mma16816(float (&c)[4], const uint32_t (&a)[4],
                                         uint32_t b0, uint32_t b1) {
    asm volatile(
        "mma.sync.aligned.m16n8k16.row.col.f32.f16.f16.f32 "
        "{%0,%1,%2,%3}, {%4,%5,%6,%7}, {%8,%9}, {%0,%1,%2,%3};"
        : "+f"(c[0]), "+f"(c[1]), "+f"(c[2]), "+f"(c[3])
        : "r"(a[0]), "r"(a[1]), "r"(a[2]), "r"(a[3]), "r"(b0), "r"(b1));
}
__device__ __forceinline__ uint32_t h2bits(half2 h) {
    return *(uint32_t*)&h;
}
// hi pair only (for wq)
__device__ __forceinline__ void cvt4h(float4 v, uint32_t& h01, uint32_t& h23) {
    h01 = h2bits(__floats2half2_rn(v.x, v.y));
    h23 = h2bits(__floats2half2_rn(v.z, v.w));
}
// hi + lo split (for x): x = hi + lo exact to ~2^-22
__device__ __forceinline__ void split4h(float4 v, uint32_t& h01, uint32_t& h23,
                                        uint32_t& l01, uint32_t& l23) {
    half2 p0 = __floats2half2_rn(v.x, v.y);
    half2 p1 = __floats2half2_rn(v.z, v.w);
    float2 f0 = __half22float2(p0);
    float2 f1 = __half22float2(p1);
    half2 q0 = __floats2half2_rn(v.x - f0.x, v.y - f0.y);
    half2 q1 = __floats2half2_rn(v.z - f1.x, v.w - f1.y);
    h01 = h2bits(p0); h23 = h2bits(p1);
    l01 = h2bits(q0); l23 = h2bits(q1);
}

// smem layout (bytes)
#define WSTRB     528            // wq row stride (264 halves)
#define XSTRB     272            // x row stride (136 halves)
#define OFF_WQH   0              // 64*528  = 33792
#define OFF_XH    33792          // 256*272 = 69632
#define OFF_XL    103424         // 69632
#define OFF_E     173056         // 128 floats
#define OFF_W     173568         // 128 floats
#define OFF_TK    174080         // 64 floats
#define OFF_BQ    174336         // 64 floats
#define OFF_ZR    174592         // 4 floats
#define ESMEM     174656

// ---------------- kernel 0: tk = tanh(wk @ x_key + bk) ----------------
__global__ void tk_kernel(const float* __restrict__ xk,
                          const float* __restrict__ wk,
                          const float* __restrict__ bk,
                          float* __restrict__ tk) {
    __shared__ float xs[Cc];
    int b = blockIdx.x;
    for (int i = threadIdx.x; i < Cc; i += blockDim.x) xs[i] = xk[b * Cc + i];
    __syncthreads();
    int o = threadIdx.x;
    if (o < CQ) {
        float s = bk[o];
        const float* wr = wk + o * Cc;
        #pragma unroll 8
        for (int c = 0; c < Cc; ++c) s += wr[c] * xs[c];
        tk[b * CQ + o] = tanhf(s);
    }
}

// ---------------- fused kernel: energy + exp + y partials (fp16, 2-pass) ----------------
// grid (32, 128): CTA = (b, 128-n tile). 256 threads = 8 warps x 16 n.
__global__ void __launch_bounds__(256)
fused_kernel(const float* __restrict__ x,
             const float* __restrict__ wq,
             const float* __restrict__ bq,
             const float* __restrict__ tk,
             float* __restrict__ energy,
             float* __restrict__ yp,
             float* __restrict__ zp) {
    extern __shared__ char sm[];
    const uint32_t sb = smem_u32(sm);
    const int tid  = threadIdx.x;
    const int warp = tid >> 5;
    const int lane = tid & 31;
    const int b    = blockIdx.y;
    const int tile = blockIdx.x;
    const int n0   = tile * NT;

    float* tk_s = (float*)(sm + OFF_TK);
    float* bq_s = (float*)(sm + OFF_BQ);
    float* e_s  = (float*)(sm + OFF_E);
    float* w_s  = (float*)(sm + OFF_W);
    float* zr_s = (float*)(sm + OFF_ZR);
    if (tid < CQ) {
        tk_s[tid] = tk[b * CQ + tid];
        bq_s[tid] = bq[tid];
    }

    // ---- stage wq (fp16 hi only) ----
    {
        const float4* wq4 = (const float4*)wq;
        #pragma unroll
        for (int f = 0; f < 16; ++f) {
            int idx = f * 256 + tid;       // 4096 float4 = 64 o x 64 j (c=4j)
            int o = idx >> 6;
            int j = idx & 63;
            float4 v = wq4[idx];
            uint32_t h01, h23;
            cvt4h(v, h01, h23);
            *(uint2*)(sm + OFF_WQH + (uint32_t)o * WSTRB + j * 8) = make_uint2(h01, h23);
        }
    }

    // accumulators: 4 m-tiles (o) x 2 n-tiles x 4
    float acc[4][2][4];
    #pragma unroll
    for (int mt = 0; mt < 4; ++mt)
        #pragma unroll
        for (int nt = 0; nt < 2; ++nt)
            #pragma unroll
            for (int e = 0; e < 4; ++e) acc[mt][nt][e] = 0.f;

    const uint32_t a_off = (uint32_t)(lane & 15) * WSTRB + (uint32_t)(lane >> 4) * 16;
    const uint32_t b_off = (uint32_t)(((lane >> 3) & 1) * 8 + (lane & 7)) * XSTRB
                         + (uint32_t)(lane >> 4) * 16 + (uint32_t)warp * 32;

    const float* xg = x + ((size_t)b * Cc) * Np + n0;

    int sc[4], sj[4];
    #pragma unroll
    for (int f = 0; f < 4; ++f) {
        int idx = f * 256 + tid;
        sc[f] = idx >> 5;
        sj[f] = idx & 31;
    }

    float4 pre[4];
    #pragma unroll
    for (int f = 0; f < 4; ++f)
        pre[f] = *(const float4*)(xg + (size_t)sc[f] * Np + 4 * sj[f]);

    for (int ch = 0; ch < 8; ++ch) {
        // convert + store chunk ch (hi/lo split of x)
        #pragma unroll
        for (int f = 0; f < 4; ++f) {
            uint32_t h01, h23, l01, l23;
            split4h(pre[f], h01, h23, l01, l23);
            uint32_t off = (uint32_t)(ch * 32 + sc[f]) * XSTRB + sj[f] * 8;
            *(uint2*)(sm + OFF_XH + off) = make_uint2(h01, h23);
            *(uint2*)(sm + OFF_XL + off) = make_uint2(l01, l23);
        }
        __syncthreads();

        // prefetch next chunk (hides under MMAs)
        if (ch < 7) {
            #pragma unroll
            for (int f = 0; f < 4; ++f)
                pre[f] = *(const float4*)(xg + (size_t)((ch + 1) * 32 + sc[f]) * Np + 4 * sj[f]);
        }

        #pragma unroll
        for (int kk = 0; kk < 2; ++kk) {
            uint32_t c_b  = (uint32_t)(ch * 32 + kk * 16) * 2;
            uint32_t krow = (uint32_t)(ch * 32 + kk * 16) * XSTRB;

            uint32_t a_h[4][4];
            #pragma unroll
            for (int mt = 0; mt < 4; ++mt)
                ldsm4(a_h[mt], sb + OFF_WQH + (uint32_t)mt * (16 * WSTRB) + c_b + a_off);
            uint32_t b_hi[4], b_lo[4];
            ldsm4t(b_hi, sb + OFF_XH + krow + b_off);
            ldsm4t(b_lo, sb + OFF_XL + krow + b_off);

            #pragma unroll
            for (int mt = 0; mt < 4; ++mt)
                #pragma unroll
                for (int nt = 0; nt < 2; ++nt) {
                    int hb = nt * 2;
                    mma16816(acc[mt][nt], a_h[mt], b_hi[hb], b_hi[hb + 1]);
                    mma16816(acc[mt][nt], a_h[mt], b_lo[hb], b_lo[hb + 1]);
                }
        }
    }

    // ---- energy epilogue ----
    {
        const int r = lane >> 2;
        float s0[2] = {0.f, 0.f};
        float s1[2] = {0.f, 0.f};
        #pragma unroll
        for (int mt = 0; mt < 4; ++mt) {
            float bq1 = bq_s[mt * 16 + r],     tk1 = tk_s[mt * 16 + r];
            float bq2 = bq_s[mt * 16 + r + 8], tk2 = tk_s[mt * 16 + r + 8];
            #pragma unroll
            for (int nt = 0; nt < 2; ++nt) {
                s0[nt] += tanhf(acc[mt][nt][0] + bq1) * tk1 + tanhf(acc[mt][nt][2] + bq2) * tk2;
                s1[nt] += tanhf(acc[mt][nt][1] + bq1) * tk1 + tanhf(acc[mt][nt][3] + bq2) * tk2;
            }
        }
        #pragma unroll
        for (int nt = 0; nt < 2; ++nt) {
            #pragma unroll
            for (int d = 4; d < 32; d <<= 1) {
                s0[nt] += __shfl_xor_sync(0xFFFFFFFFu, s0[nt], d);
                s1[nt] += __shfl_xor_sync(0xFFFFFFFFu, s1[nt], d);
            }
        }
        if (lane < 4) {
            #pragma unroll
            for (int nt = 0; nt < 2; ++nt) {
                int nl = warp * 16 + nt * 8 + 2 * lane;
                float2 ev = make_float2(s0[nt], s1[nt]);
                *(float2*)(e_s + nl) = ev;
                *(float2*)(energy + (size_t)b * Np + n0 + nl) = ev;
            }
        }
    }
    __syncthreads();

    // ---- w = exp(e) (|e| < 64, no overflow) + Z partial ----
    if (tid < NT) {
        float w = expf(e_s[tid]);
        w_s[tid] = w;
        float s = w;
        #pragma unroll
        for (int d = 16; d; d >>= 1) s += __shfl_xor_sync(0xFFFFFFFFu, s, d);
        if (lane == 0) zr_s[tid >> 5] = s;
    }
    __syncthreads();
    if (tid == 0) zp[b * NTILES + tile] = zr_s[0] + zr_s[1] + zr_s[2] + zr_s[3];

    // ---- y partial: y_p[c] = sum_n x[c,n] * w[n]  (x = hi + lo from smem) ----
    {
        int c = tid;
        const uint2* hrow = (const uint2*)(sm + OFF_XH + (uint32_t)c * XSTRB);
        const uint2* lrow = (const uint2*)(sm + OFF_XL + (uint32_t)c * XSTRB);
        float accy = 0.f;
        #pragma unroll 8
        for (int j = 0; j < 32; ++j) {
            uint2 h = hrow[j];
            uint2 l = lrow[j];
            float4 w4 = *(const float4*)(w_s + 4 * j);
            float2 h0 = __half22float2(*(half2*)&h.x);
            float2 h1 = __half22float2(*(half2*)&h.y);
            float2 l0 = __half22float2(*(half2*)&l.x);
            float2 l1 = __half22float2(*(half2*)&l.y);
            accy = fmaf(h0.x + l0.x, w4.x, accy);
            accy = fmaf(h0.y + l0.y, w4.y, accy);
            accy = fmaf(h1.x + l1.x, w4.z, accy);
            accy = fmaf(h1.y + l1.y, w4.w, accy);
        }
        yp[((size_t)b * NTILES + tile) * Cc + c] = accy;
    }
}

// ---------------- kernel B: attention = softmax(energy) ----------------
__global__ void softmax_kernel(const float* __restrict__ energy,
                               float* __restrict__ att) {
    __shared__ float red[256];
    int b = blockIdx.x, t = threadIdx.x;
    const float4* e4 = (const float4*)(energy + (size_t)b * Np);
    float4 v[4];
    float m = -INFINITY;
    #pragma unroll
    for (int k = 0; k < 4; ++k) {
        v[k] = e4[k * 256 + t];
        m = fmaxf(m, fmaxf(fmaxf(v[k].x, v[k].y), fmaxf(v[k].z, v[k].w)));
    }
    red[t] = m; __syncthreads();
    for (int off = 128; off; off >>= 1) {
        if (t < off) red[t] = fmaxf(red[t], red[t + off]);
        __syncthreads();
    }
    m = red[0]; __syncthreads();
    float s = 0.f;
    #pragma unroll
    for (int k = 0; k < 4; ++k)
        s += expf(v[k].x - m) + expf(v[k].y - m) + expf(v[k].z - m) + expf(v[k].w - m);
    red[t] = s; __syncthreads();
    for (int off = 128; off; off >>= 1) {
        if (t < off) red[t] += red[t + off];
        __syncthreads();
    }
    float inv = 1.f / red[0];
    float4* a4 = (float4*)(att + (size_t)b * Np);
    #pragma unroll
    for (int k = 0; k < 4; ++k) {
        float4 o;
        o.x = expf(v[k].x - m) * inv;
        o.y = expf(v[k].y - m) * inv;
        o.z = expf(v[k].z - m) * inv;
        o.w = expf(v[k].w - m) * inv;
        a4[k * 256 + t] = o;
    }
}

// ---------------- kernel D1: reduce y partials; d = x_key - (wv @ y + bv) ----------------
// grid (4, Bn): block computes 64 outputs c; y/Z reduce duplicated per block.
__global__ void d_kernel(const float* __restrict__ xk,
                         const float* __restrict__ wv,
                         const float* __restrict__ bv,
                         const float* __restrict__ yp,
                         const float* __restrict__ zp,
                         float* __restrict__ d) {
    __shared__ float ys[Cc];
    int b = blockIdx.y, cq = blockIdx.x, t = threadIdx.x;
    {
        float Z = 0.f;
        #pragma unroll 8
        for (int tt = 0; tt < NTILES; ++tt) Z += zp[b * NTILES + tt];
        float s = 0.f;
        #pragma unroll 8
        for (int tt = 0; tt < NTILES; ++tt)
            s += yp[((size_t)b * NTILES + tt) * Cc + t];
        ys[t] = s / Z;
    }
    __syncthreads();
    int warp = t >> 5, lane = t & 31;
    #pragma unroll
    for (int i = 0; i < 8; ++i) {
        int c = cq * 64 + warp * 8 + i;
        float s = 0.f;
        #pragma unroll
        for (int k = 0; k < 8; ++k) {
            int cp = k * 32 + lane;
            s += wv[(size_t)c * Cc + cp] * ys[cp];
        }
        #pragma unroll
        for (int off = 16; off; off >>= 1) s += __shfl_down_sync(0xFFFFFFFFu, s, off);
        if (lane == 0) d[b * Cc + c] = xk[b * Cc + c] - (s + bv[c]);
    }
}

// ---------------- kernel D2: BN + ReLU + residual ----------------
__global__ void bn_out_kernel(const float* __restrict__ d,
                              const float* __restrict__ wt,
                              const float* __restrict__ bt,
                              const float* __restrict__ gamma,
                              const float* __restrict__ beta,
                              const float* __restrict__ xk,
                              float* __restrict__ out) {
    __shared__ float wts[Cc];
    __shared__ float ts[Bn];
    __shared__ float r1[Bn];
    __shared__ float r2[Bn];
    int c = blockIdx.x, t = threadIdx.x;
    wts[t] = wt[(size_t)c * Cc + t];
    wts[t + 128] = wt[(size_t)c * Cc + t + 128];
    __syncthreads();
    int warp = t >> 5, lane = t & 31;
    for (int i = 0; i < 32; ++i) {
        int b = warp * 32 + i;
        float s = 0.f;
        #pragma unroll
        for (int k = 0; k < 8; ++k) {
            int cp = k * 32 + lane;
            s += wts[cp] * d[b * Cc + cp];
        }
        #pragma unroll
        for (int off = 16; off; off >>= 1) s += __shfl_down_sync(0xFFFFFFFFu, s, off);
        if (lane == 0) ts[b] = s + bt[c];
    }
    __syncthreads();
    float tv = ts[t];
    r1[t] = tv; r2[t] = tv * tv;
    __syncthreads();
    for (int off = 64; off; off >>= 1) {
        if (t < off) { r1[t] += r1[t + off]; r2[t] += r2[t + off]; }
        __syncthreads();
    }
    float mean = r1[0] * (1.f / Bn);
    float var  = r2[0] * (1.f / Bn) - mean * mean;
    float nrm  = (tv - mean) * rsqrtf(var + BN_EPS) * gamma[c] + beta[c];
    out[t * Cc + c] = xk[t * Cc + c] + fmaxf(nrm, 0.f);
}

// ---------------- launch ----------------
extern "C" void kernel_launch(void* const* d_in, const int* in_sizes, int n_in,
                              void* d_out, int out_size) {
    const float* x     = (const float*)d_in[0];
    const float* xkey  = (const float*)d_in[1];
    const float* wq    = (const float*)d_in[2];
    const float* bq    = (const float*)d_in[3];
    const float* wk    = (const float*)d_in[4];
    const float* bk    = (const float*)d_in[5];
    const float* wv    = (const float*)d_in[6];
    const float* bv    = (const float*)d_in[7];
    const float* wt    = (const float*)d_in[8];
    const float* bt    = (const float*)d_in[9];
    const float* gamma = (const float*)d_in[10];
    const float* beta  = (const float*)d_in[11];

    float* out_final = (float*)d_out;
    float* out_att   = (float*)d_out + Bn * Cc;

    float *tk, *energy, *yp, *zp, *dd;
    cudaGetSymbolAddress((void**)&tk,     g_tk);
    cudaGetSymbolAddress((void**)&energy, g_energy);
    cudaGetSymbolAddress((void**)&yp,     g_yp);
    cudaGetSymbolAddress((void**)&zp,     g_zp);
    cudaGetSymbolAddress((void**)&dd,     g_d);

    cudaFuncSetAttribute(fused_kernel, cudaFuncAttributeMaxDynamicSharedMemorySize, ESMEM);

    tk_kernel<<<Bn, 64>>>(xkey, wk, bk, tk);
    fused_kernel<<<dim3(NTILES, Bn), 256, ESMEM>>>(x, wq, bq, tk, energy, yp, zp);
    softmax_kernel<<<Bn, 256>>>(energy, out_att);
    d_kernel<<<dim3(4, Bn), 256>>>(xkey, wv, bv, yp, zp, dd);
    bn_out_kernel<<<Cc, 128>>>(dd, wt, bt, gamma, beta, xkey, out_final);
}